// round 7
// baseline (speedup 1.0000x reference)
#include <cuda_runtime.h>
#include <cstdint>

// Problem constants (fixed-shape problem)
#define DDIM   512          // feature dim
#define BNUM   64           // batch / segment count
#define LSEQ   2048         // max_length
#define ACC_ELEMS (BNUM * DDIM)   // 32768 floats = 128 KB
#define K1_GRID 148         // one CTA per SM, single wave
#define K1_THREADS 256      // each thread owns 2 columns (float2)

// Scratch (allocation-free: __device__ globals)
__device__ float g_partials[K1_GRID * ACC_ELEMS];   // ~19.4 MB
__device__ float g_x[ACC_ELEMS];                    // final [64, 512]

// ---------------------------------------------------------------------------
// K1: privatized shared-memory segment sum. Each CTA owns a full [64 x 512]
// fp32 accumulator in dynamic smem. Thread t exclusively owns float2 column
// slot t, so no two threads ever touch the same smem word -> no atomics.
// ---------------------------------------------------------------------------
template <typename IT>
__device__ __forceinline__ void accum_loop(const float2* __restrict__ gh,
                                           const IT* __restrict__ tp,
                                           int i0, int i1, int tid,
                                           float* __restrict__ sacc) {
#pragma unroll 4
    for (int i = i0; i < i1; ++i) {
        const int b1 = (int)__ldg(&tp[2 * i]);
        const int b2 = (int)__ldg(&tp[2 * i + 1]);
        const float2 v = __ldg(&gh[(size_t)i * (DDIM / 2) + tid]);
        if (b1 == b2) {   // warp-uniform branch (indices are uniform per warp)
            float2* p = (float2*)(sacc + b1 * DDIM) + tid;
            float2 a = *p;
            a.x += 2.0f * v.x; a.y += 2.0f * v.y;
            *p = a;
        } else {
            float2* p = (float2*)(sacc + b1 * DDIM) + tid;
            float2* q = (float2*)(sacc + b2 * DDIM) + tid;
            float2 a = *p; a.x += v.x; a.y += v.y; *p = a;
            float2 c = *q; c.x += v.x; c.y += v.y; *q = c;
        }
    }
}

__global__ void __launch_bounds__(K1_THREADS, 1)
k1_accum(const float* __restrict__ gcn, const void* __restrict__ tp, int nnodes) {
    extern __shared__ float sacc[];   // 128 KB
    const int tid = threadIdx.x;

    // zero private accumulator
    {
        float4* z = (float4*)sacc;
#pragma unroll
        for (int i = tid; i < ACC_ELEMS / 4; i += K1_THREADS)
            z[i] = make_float4(0.f, 0.f, 0.f, 0.f);
    }

    // Runtime index-dtype detection: values are in [0, 64). If the buffer is
    // int32 but read as u64, a sample is >= 2^32 with prob 63/64 per probe.
    // 64 probes => misdetection prob (1/64)^64 ~ 0.
    __shared__ int s_is64;
    if (tid == 0) {
        const unsigned long long* p = (const unsigned long long*)tp;
        int f = 1;
        for (int j = 0; j < 64; ++j)
            if (p[j] >= 64ull) { f = 0; break; }
        s_is64 = f;
    }
    __syncthreads();
    const bool is64 = (s_is64 != 0);

    const int chunk = (nnodes + K1_GRID - 1) / K1_GRID;
    const int i0 = blockIdx.x * chunk;
    const int i1 = min(i0 + chunk, nnodes);

    const float2* gh = (const float2*)gcn;
    if (is64)
        accum_loop<long long>(gh, (const long long*)tp, i0, i1, tid, sacc);
    else
        accum_loop<int>(gh, (const int*)tp, i0, i1, tid, sacc);

    __syncthreads();
    // flush private partial (zeros if this CTA had an empty range)
    float4* dst = (float4*)(g_partials + (size_t)blockIdx.x * ACC_ELEMS);
    const float4* src = (const float4*)sacc;
#pragma unroll
    for (int i = tid; i < ACC_ELEMS / 4; i += K1_THREADS)
        dst[i] = src[i];
}

// ---------------------------------------------------------------------------
// K2: reduce 148 partials -> g_x. Fully coalesced (adjacent threads read
// adjacent floats within each partial), deterministic order.
// ---------------------------------------------------------------------------
__global__ void __launch_bounds__(256) k2_reduce() {
    const int idx = blockIdx.x * 256 + threadIdx.x;   // 0 .. 32767
    float s = 0.f;
#pragma unroll 4
    for (int c = 0; c < K1_GRID; ++c)
        s += g_partials[(size_t)c * ACC_ELEMS + idx];
    g_x[idx] = s;
}

// ---------------------------------------------------------------------------
// K3: broadcast x[b,:] across L. Each CTA handles (b, 64 rows of L); each
// thread caches its float4 of the row in a register (g_x is L2-resident
// after K2) and streams it out with __stcs stores.
// ---------------------------------------------------------------------------
__global__ void __launch_bounds__(256) k3_bcast(float* __restrict__ out) {
    const int b = blockIdx.y;
    const int l0 = blockIdx.x * 64;

    const int j = threadIdx.x & 127;    // float4 column 0..127
    const int r = threadIdx.x >> 7;     // row parity (0/1)
    const float4 v = __ldg((const float4*)(g_x + b * DDIM) + j);

    float4* o = (float4*)out + ((size_t)b * LSEQ + l0 + r) * (DDIM / 4) + j;
#pragma unroll
    for (int l = 0; l < 64; l += 2) {
        __stcs(o, v);                   // streaming store: write-once data
        o += 2 * (DDIM / 4);
    }
}

// ---------------------------------------------------------------------------
// Launch. Inputs (metadata order): gcn_hidden f32 [N*512], token_position
// int64/int32 [2N], batch_size, max_length, token_position2 (unused).
// ---------------------------------------------------------------------------
extern "C" void kernel_launch(void* const* d_in, const int* in_sizes, int n_in,
                              void* d_out, int out_size) {
    const float* gcn = (const float*)d_in[0];
    const void*  tp  = d_in[1];
    const int nnodes = in_sizes[0] / DDIM;   // N = 100000

    cudaFuncSetAttribute(k1_accum, cudaFuncAttributeMaxDynamicSharedMemorySize,
                         ACC_ELEMS * (int)sizeof(float));

    k1_accum<<<K1_GRID, K1_THREADS, ACC_ELEMS * sizeof(float)>>>(gcn, tp, nnodes);
    k2_reduce<<<ACC_ELEMS / 256, 256>>>();
    dim3 g3(LSEQ / 64, BNUM);
    k3_bcast<<<g3, 256>>>((float*)d_out);
}

// round 8
// speedup vs baseline: 1.1093x; 1.1093x over previous
#include <cuda_runtime.h>
#include <cstdint>

// Problem constants (fixed-shape problem)
#define DDIM   512          // feature dim
#define BNUM   64           // batch / segment count
#define LSEQ   2048         // max_length
#define ACC_ELEMS (BNUM * DDIM)   // 32768 floats = 128 KB
#define K1_GRID 148         // one CTA per SM, single wave
#define K1_THREADS 512      // each thread owns exactly ONE float column
#define UBATCH 16           // nodes batched per inner iteration (MLP)

// Scratch (allocation-free: __device__ globals)
__device__ float g_partials[K1_GRID * ACC_ELEMS];   // ~19.4 MB
__device__ float g_x[ACC_ELEMS];                    // final [64, 512]

// ---------------------------------------------------------------------------
// Vectorized index-pair loads (one load per node instead of two)
// ---------------------------------------------------------------------------
__device__ __forceinline__ void load_idx(const int* __restrict__ tp, int i,
                                         int& b1, int& b2) {
    const int2 t = __ldg((const int2*)tp + i);
    b1 = t.x; b2 = t.y;
}
__device__ __forceinline__ void load_idx(const long long* __restrict__ tp, int i,
                                         int& b1, int& b2) {
    const longlong2 t = __ldg((const longlong2*)tp + i);
    b1 = (int)t.x; b2 = (int)t.y;
}

// ---------------------------------------------------------------------------
// K1 inner loop: batch UBATCH node values + indices into registers first
// (raises memory-level parallelism to 16 outstanding lines per warp), then
// apply the smem RMWs. Thread tid exclusively owns column tid -> no
// collisions, no atomics.
// ---------------------------------------------------------------------------
template <typename IT>
__device__ __forceinline__ void accum_loop(const float* __restrict__ gh,
                                           const IT* __restrict__ tp,
                                           int i0, int i1, int tid,
                                           float* __restrict__ sacc) {
    int i = i0;
    for (; i + UBATCH <= i1; i += UBATCH) {
        float v[UBATCH];
        int b1[UBATCH], b2[UBATCH];
#pragma unroll
        for (int u = 0; u < UBATCH; ++u)
            v[u] = __ldg(&gh[(size_t)(i + u) * DDIM + tid]);
#pragma unroll
        for (int u = 0; u < UBATCH; ++u)
            load_idx(tp, i + u, b1[u], b2[u]);
#pragma unroll
        for (int u = 0; u < UBATCH; ++u) {
            if (b1[u] == b2[u]) {          // warp-uniform branch
                sacc[b1[u] * DDIM + tid] += 2.0f * v[u];
            } else {
                sacc[b1[u] * DDIM + tid] += v[u];
                sacc[b2[u] * DDIM + tid] += v[u];
            }
        }
    }
    // tail
    for (; i < i1; ++i) {
        const float v = __ldg(&gh[(size_t)i * DDIM + tid]);
        int b1, b2;
        load_idx(tp, i, b1, b2);
        if (b1 == b2) {
            sacc[b1 * DDIM + tid] += 2.0f * v;
        } else {
            sacc[b1 * DDIM + tid] += v;
            sacc[b2 * DDIM + tid] += v;
        }
    }
}

__global__ void __launch_bounds__(K1_THREADS, 1)
k1_accum(const float* __restrict__ gcn, const void* __restrict__ tp, int nnodes) {
    extern __shared__ float sacc[];   // 128 KB
    const int tid = threadIdx.x;

    // zero private accumulator
    {
        float4* z = (float4*)sacc;
#pragma unroll
        for (int i = tid; i < ACC_ELEMS / 4; i += K1_THREADS)
            z[i] = make_float4(0.f, 0.f, 0.f, 0.f);
    }

    // Runtime index-dtype detection: values are in [0, 64). If the buffer is
    // int32 but read as u64, a sample is >= 2^32 with prob 63/64 per probe.
    // 64 probes => misdetection prob (1/64)^64 ~ 0.
    __shared__ int s_is64;
    if (tid == 0) {
        const unsigned long long* p = (const unsigned long long*)tp;
        int f = 1;
        for (int j = 0; j < 64; ++j)
            if (p[j] >= 64ull) { f = 0; break; }
        s_is64 = f;
    }
    __syncthreads();
    const bool is64 = (s_is64 != 0);

    const int chunk = (nnodes + K1_GRID - 1) / K1_GRID;
    const int i0 = blockIdx.x * chunk;
    const int i1 = min(i0 + chunk, nnodes);

    if (is64)
        accum_loop<long long>(gcn, (const long long*)tp, i0, i1, tid, sacc);
    else
        accum_loop<int>(gcn, (const int*)tp, i0, i1, tid, sacc);

    __syncthreads();
    // flush private partial (zeros if this CTA had an empty range)
    float4* dst = (float4*)(g_partials + (size_t)blockIdx.x * ACC_ELEMS);
    const float4* src = (const float4*)sacc;
#pragma unroll
    for (int i = tid; i < ACC_ELEMS / 4; i += K1_THREADS)
        dst[i] = src[i];
}

// ---------------------------------------------------------------------------
// K2: reduce 148 partials -> g_x. Fully coalesced (adjacent threads read
// adjacent floats within each partial), deterministic order.
// ---------------------------------------------------------------------------
__global__ void __launch_bounds__(256) k2_reduce() {
    const int idx = blockIdx.x * 256 + threadIdx.x;   // 0 .. 32767
    float s = 0.f;
#pragma unroll 4
    for (int c = 0; c < K1_GRID; ++c)
        s += g_partials[(size_t)c * ACC_ELEMS + idx];
    g_x[idx] = s;
}

// ---------------------------------------------------------------------------
// K3: broadcast x[b,:] across L. Each CTA handles (b, 64 rows of L); each
// thread caches its float4 of the row in a register (g_x is L2-resident
// after K2) and streams it out with __stcs stores.
// ---------------------------------------------------------------------------
__global__ void __launch_bounds__(256) k3_bcast(float* __restrict__ out) {
    const int b = blockIdx.y;
    const int l0 = blockIdx.x * 64;

    const int j = threadIdx.x & 127;    // float4 column 0..127
    const int r = threadIdx.x >> 7;     // row parity (0/1)
    const float4 v = __ldg((const float4*)(g_x + b * DDIM) + j);

    float4* o = (float4*)out + ((size_t)b * LSEQ + l0 + r) * (DDIM / 4) + j;
#pragma unroll
    for (int l = 0; l < 64; l += 2) {
        __stcs(o, v);                   // streaming store: write-once data
        o += 2 * (DDIM / 4);
    }
}

// ---------------------------------------------------------------------------
// Launch. Inputs (metadata order): gcn_hidden f32 [N*512], token_position
// int64/int32 [2N], batch_size, max_length, token_position2 (unused).
// ---------------------------------------------------------------------------
extern "C" void kernel_launch(void* const* d_in, const int* in_sizes, int n_in,
                              void* d_out, int out_size) {
    const float* gcn = (const float*)d_in[0];
    const void*  tp  = d_in[1];
    const int nnodes = in_sizes[0] / DDIM;   // N = 100000

    cudaFuncSetAttribute(k1_accum, cudaFuncAttributeMaxDynamicSharedMemorySize,
                         ACC_ELEMS * (int)sizeof(float));

    k1_accum<<<K1_GRID, K1_THREADS, ACC_ELEMS * sizeof(float)>>>(gcn, tp, nnodes);
    k2_reduce<<<ACC_ELEMS / 256, 256>>>();
    dim3 g3(LSEQ / 64, BNUM);
    k3_bcast<<<g3, 256>>>((float*)d_out);
}

// round 9
// speedup vs baseline: 1.4373x; 1.2957x over previous
#include <cuda_runtime.h>
#include <cstdint>

// Problem constants (fixed-shape problem)
#define DDIM   512          // feature dim
#define BNUM   64           // batch / segment count
#define LSEQ   2048         // max_length
#define ACC_ELEMS (BNUM * DDIM)   // 32768 floats = 128 KB
#define K1_GRID 148         // one CTA per SM, single wave
#define K1_THREADS 512      // each thread owns exactly ONE float column
#define UB 8                // nodes per pipeline batch (double-buffered)
#define MAX_CHUNK 688       // > ceil(100000/148) = 676, padded

#define ACC_BYTES   (ACC_ELEMS * 4)
#define SMEM_BYTES  (ACC_BYTES + MAX_CHUNK * 8)   // accumulator + staged int2 idx

// Scratch (allocation-free: __device__ globals)
__device__ float g_partials[K1_GRID * ACC_ELEMS];   // ~19.4 MB
__device__ float g_x[ACC_ELEMS];                    // final [64, 512]

__global__ void __launch_bounds__(K1_THREADS, 1)
k1_accum(const float* __restrict__ gcn, const void* __restrict__ tp, int nnodes) {
    extern __shared__ float sacc[];                    // 128 KB accumulator
    int2* sidx = (int2*)((char*)sacc + ACC_BYTES);     // staged index pairs
    const int tid = threadIdx.x;

    // zero private accumulator
    {
        float4* z = (float4*)sacc;
#pragma unroll
        for (int i = tid; i < ACC_ELEMS / 4; i += K1_THREADS)
            z[i] = make_float4(0.f, 0.f, 0.f, 0.f);
    }

    // Runtime index-dtype detection: values are in [0, 64). If the buffer is
    // int32 but read as u64, a sample is >= 2^32 with prob 63/64 per probe.
    // 64 probes => misdetection prob (1/64)^64 ~ 0.
    __shared__ int s_is64;
    if (tid == 0) {
        const unsigned long long* p = (const unsigned long long*)tp;
        int f = 1;
        for (int j = 0; j < 64; ++j)
            if (p[j] >= 64ull) { f = 0; break; }
        s_is64 = f;
    }
    __syncthreads();

    const int chunk = (nnodes + K1_GRID - 1) / K1_GRID;
    const int i0 = blockIdx.x * chunk;
    const int i1 = min(i0 + chunk, nnodes);
    const int cnt = i1 - i0;   // may be <= 0 for trailing CTAs

    // Stage this CTA's index pairs to smem as int2 (dtype resolved here, once)
    if (s_is64) {
        const longlong2* p = (const longlong2*)tp;
        for (int j = tid; j < cnt; j += K1_THREADS) {
            longlong2 t = __ldg(p + (i0 + j));
            sidx[j] = make_int2((int)t.x, (int)t.y);
        }
    } else {
        const int2* p = (const int2*)tp;
        for (int j = tid; j < cnt; j += K1_THREADS)
            sidx[j] = __ldg(p + (i0 + j));
    }
    __syncthreads();

    // ---- software-pipelined hot loop: double-buffered 8-node batches ----
    const float* gh = gcn + (size_t)i0 * DDIM + tid;

    float va[UB], vb[UB];
    int2  ia[UB], ib[UB];

#define LOAD_BATCH(V, I, base)                                              \
    {                                                                       \
        _Pragma("unroll")                                                   \
        for (int u = 0; u < UB; ++u)                                        \
            V[u] = __ldg(gh + (size_t)((base) + u) * DDIM);                 \
        _Pragma("unroll")                                                   \
        for (int u = 0; u < UB; ++u)                                        \
            I[u] = sidx[(base) + u];                                        \
    }

#define PROC_BATCH(V, I)                                                    \
    {                                                                       \
        _Pragma("unroll")                                                   \
        for (int u = 0; u < UB; ++u) {                                      \
            sacc[I[u].x * DDIM + tid] += V[u];                              \
            sacc[I[u].y * DDIM + tid] += V[u];                              \
        }                                                                   \
    }

    const int n_full = cnt > 0 ? cnt / UB : 0;
    int k = 0;
    if (n_full > 0) LOAD_BATCH(va, ia, 0);
    for (; k + 2 <= n_full; k += 2) {
        LOAD_BATCH(vb, ib, (k + 1) * UB);
        PROC_BATCH(va, ia);
        if (k + 2 < n_full) LOAD_BATCH(va, ia, (k + 2) * UB);
        PROC_BATCH(vb, ib);
    }
    if (k < n_full) PROC_BATCH(va, ia);   // odd batch, already loaded

    // tail nodes
    for (int j = n_full * UB; j < cnt; ++j) {
        const float v = __ldg(gh + (size_t)j * DDIM);
        const int2 b = sidx[j];
        sacc[b.x * DDIM + tid] += v;
        sacc[b.y * DDIM + tid] += v;
    }

#undef LOAD_BATCH
#undef PROC_BATCH

    __syncthreads();
    // flush private partial (zeros if this CTA had an empty range)
    float4* dst = (float4*)(g_partials + (size_t)blockIdx.x * ACC_ELEMS);
    const float4* src = (const float4*)sacc;
#pragma unroll
    for (int i = tid; i < ACC_ELEMS / 4; i += K1_THREADS)
        dst[i] = src[i];
}

// ---------------------------------------------------------------------------
// K2: reduce 148 partials -> g_x. Fully coalesced, deterministic order.
// ---------------------------------------------------------------------------
__global__ void __launch_bounds__(256) k2_reduce() {
    const int idx = blockIdx.x * 256 + threadIdx.x;   // 0 .. 32767
    float s = 0.f;
#pragma unroll 4
    for (int c = 0; c < K1_GRID; ++c)
        s += g_partials[(size_t)c * ACC_ELEMS + idx];
    g_x[idx] = s;
}

// ---------------------------------------------------------------------------
// K3: broadcast x[b,:] across L. Each CTA handles (b, 64 rows of L); each
// thread caches its float4 of the row in a register (g_x is L2-resident
// after K2) and streams it out with __stcs stores.
// ---------------------------------------------------------------------------
__global__ void __launch_bounds__(256) k3_bcast(float* __restrict__ out) {
    const int b = blockIdx.y;
    const int l0 = blockIdx.x * 64;

    const int j = threadIdx.x & 127;    // float4 column 0..127
    const int r = threadIdx.x >> 7;     // row parity (0/1)
    const float4 v = __ldg((const float4*)(g_x + b * DDIM) + j);

    float4* o = (float4*)out + ((size_t)b * LSEQ + l0 + r) * (DDIM / 4) + j;
#pragma unroll
    for (int l = 0; l < 64; l += 2) {
        __stcs(o, v);                   // streaming store: write-once data
        o += 2 * (DDIM / 4);
    }
}

// ---------------------------------------------------------------------------
// Launch. Inputs (metadata order): gcn_hidden f32 [N*512], token_position
// int64/int32 [2N], batch_size, max_length, token_position2 (unused).
// ---------------------------------------------------------------------------
extern "C" void kernel_launch(void* const* d_in, const int* in_sizes, int n_in,
                              void* d_out, int out_size) {
    const float* gcn = (const float*)d_in[0];
    const void*  tp  = d_in[1];
    const int nnodes = in_sizes[0] / DDIM;   // N = 100000

    cudaFuncSetAttribute(k1_accum, cudaFuncAttributeMaxDynamicSharedMemorySize,
                         SMEM_BYTES);

    k1_accum<<<K1_GRID, K1_THREADS, SMEM_BYTES>>>(gcn, tp, nnodes);
    k2_reduce<<<ACC_ELEMS / 256, 256>>>();
    dim3 g3(LSEQ / 64, BNUM);
    k3_bcast<<<g3, 256>>>((float*)d_out);
}

// round 10
// speedup vs baseline: 1.4430x; 1.0040x over previous
#include <cuda_runtime.h>
#include <cstdint>

// Problem constants (fixed-shape problem)
#define DDIM   512          // feature dim
#define BNUM   64           // batch / segment count
#define LSEQ   2048         // max_length
#define ACC_ELEMS (BNUM * DDIM)   // 32768 floats = 128 KB
#define K1_GRID 148         // one CTA per SM, single wave
#define K1_THREADS 512      // each thread owns exactly ONE float column
#define UB 8                // nodes per pipeline batch (double-buffered)
#define MAX_CHUNK 688       // > ceil(100000/148) = 676, padded

#define ACC_BYTES   (ACC_ELEMS * 4)
#define SMEM_BYTES  (ACC_BYTES + MAX_CHUNK * 8)   // accumulator + staged int2 idx

// Scratch (allocation-free: __device__ globals)
__device__ float g_partials[K1_GRID * ACC_ELEMS];   // ~19.4 MB
__device__ float g_x[ACC_ELEMS];                    // final [64, 512]

__global__ void __launch_bounds__(K1_THREADS, 1)
k1_accum(const float* __restrict__ gcn, const void* __restrict__ tp, int nnodes) {
    extern __shared__ float sacc[];                    // 128 KB accumulator
    int2* sidx = (int2*)((char*)sacc + ACC_BYTES);     // staged index pairs
    const int tid = threadIdx.x;

    // zero private accumulator
    {
        float4* z = (float4*)sacc;
#pragma unroll
        for (int i = tid; i < ACC_ELEMS / 4; i += K1_THREADS)
            z[i] = make_float4(0.f, 0.f, 0.f, 0.f);
    }

    // Runtime index-dtype detection: values are in [0, 64). If the buffer is
    // int32 but read as u64, a sample is >= 2^32 with prob 63/64 per probe.
    // 64 probes => misdetection prob (1/64)^64 ~ 0.
    __shared__ int s_is64;
    if (tid == 0) {
        const unsigned long long* p = (const unsigned long long*)tp;
        int f = 1;
        for (int j = 0; j < 64; ++j)
            if (p[j] >= 64ull) { f = 0; break; }
        s_is64 = f;
    }
    __syncthreads();

    const int chunk = (nnodes + K1_GRID - 1) / K1_GRID;
    const int i0 = blockIdx.x * chunk;
    const int i1 = min(i0 + chunk, nnodes);
    const int cnt = i1 - i0;   // may be <= 0 for trailing CTAs

    // Stage this CTA's index pairs to smem as int2 (dtype resolved here, once)
    if (s_is64) {
        const longlong2* p = (const longlong2*)tp;
        for (int j = tid; j < cnt; j += K1_THREADS) {
            longlong2 t = __ldg(p + (i0 + j));
            sidx[j] = make_int2((int)t.x, (int)t.y);
        }
    } else {
        const int2* p = (const int2*)tp;
        for (int j = tid; j < cnt; j += K1_THREADS)
            sidx[j] = __ldg(p + (i0 + j));
    }
    __syncthreads();

    // ---- software-pipelined hot loop: double-buffered 8-node batches ----
    const float* gh = gcn + (size_t)i0 * DDIM + tid;

    float va[UB], vb[UB];
    int2  ia[UB], ib[UB];

#define LOAD_BATCH(V, I, base)                                              \
    {                                                                       \
        _Pragma("unroll")                                                   \
        for (int u = 0; u < UB; ++u)                                        \
            V[u] = __ldg(gh + (size_t)((base) + u) * DDIM);                 \
        _Pragma("unroll")                                                   \
        for (int u = 0; u < UB; ++u)                                        \
            I[u] = sidx[(base) + u];                                        \
    }

#define PROC_BATCH(V, I)                                                    \
    {                                                                       \
        _Pragma("unroll")                                                   \
        for (int u = 0; u < UB; ++u) {                                      \
            sacc[I[u].x * DDIM + tid] += V[u];                              \
            sacc[I[u].y * DDIM + tid] += V[u];                              \
        }                                                                   \
    }

    const int n_full = cnt > 0 ? cnt / UB : 0;
    int k = 0;
    if (n_full > 0) LOAD_BATCH(va, ia, 0);
    for (; k + 2 <= n_full; k += 2) {
        LOAD_BATCH(vb, ib, (k + 1) * UB);
        PROC_BATCH(va, ia);
        if (k + 2 < n_full) LOAD_BATCH(va, ia, (k + 2) * UB);
        PROC_BATCH(vb, ib);
    }
    if (k < n_full) PROC_BATCH(va, ia);   // odd batch, already loaded

    // tail nodes
    for (int j = n_full * UB; j < cnt; ++j) {
        const float v = __ldg(gh + (size_t)j * DDIM);
        const int2 b = sidx[j];
        sacc[b.x * DDIM + tid] += v;
        sacc[b.y * DDIM + tid] += v;
    }

#undef LOAD_BATCH
#undef PROC_BATCH

    __syncthreads();
    // flush private partial (zeros if this CTA had an empty range)
    float4* dst = (float4*)(g_partials + (size_t)blockIdx.x * ACC_ELEMS);
    const float4* src = (const float4*)sacc;
#pragma unroll
    for (int i = tid; i < ACC_ELEMS / 4; i += K1_THREADS)
        dst[i] = src[i];
}

// ---------------------------------------------------------------------------
// K2: reduce 148 partials -> g_x. Fully coalesced, deterministic order.
// ---------------------------------------------------------------------------
__global__ void __launch_bounds__(256) k2_reduce() {
    const int idx = blockIdx.x * 256 + threadIdx.x;   // 0 .. 32767
    float s = 0.f;
#pragma unroll 4
    for (int c = 0; c < K1_GRID; ++c)
        s += g_partials[(size_t)c * ACC_ELEMS + idx];
    g_x[idx] = s;
}

// ---------------------------------------------------------------------------
// K3: broadcast x[b,:] across L. Each CTA handles (b, 64 rows of L); each
// thread caches its float4 of the row in a register (g_x is L2-resident
// after K2) and streams it out with __stcs stores.
// ---------------------------------------------------------------------------
__global__ void __launch_bounds__(256) k3_bcast(float* __restrict__ out) {
    const int b = blockIdx.y;
    const int l0 = blockIdx.x * 64;

    const int j = threadIdx.x & 127;    // float4 column 0..127
    const int r = threadIdx.x >> 7;     // row parity (0/1)
    const float4 v = __ldg((const float4*)(g_x + b * DDIM) + j);

    float4* o = (float4*)out + ((size_t)b * LSEQ + l0 + r) * (DDIM / 4) + j;
#pragma unroll
    for (int l = 0; l < 64; l += 2) {
        __stcs(o, v);                   // streaming store: write-once data
        o += 2 * (DDIM / 4);
    }
}

// ---------------------------------------------------------------------------
// Launch. Inputs (metadata order): gcn_hidden f32 [N*512], token_position
// int64/int32 [2N], batch_size, max_length, token_position2 (unused).
// ---------------------------------------------------------------------------
extern "C" void kernel_launch(void* const* d_in, const int* in_sizes, int n_in,
                              void* d_out, int out_size) {
    const float* gcn = (const float*)d_in[0];
    const void*  tp  = d_in[1];
    const int nnodes = in_sizes[0] / DDIM;   // N = 100000

    cudaFuncSetAttribute(k1_accum, cudaFuncAttributeMaxDynamicSharedMemorySize,
                         SMEM_BYTES);

    k1_accum<<<K1_GRID, K1_THREADS, SMEM_BYTES>>>(gcn, tp, nnodes);
    k2_reduce<<<ACC_ELEMS / 256, 256>>>();
    dim3 g3(LSEQ / 64, BNUM);
    k3_bcast<<<g3, 256>>>((float*)d_out);
}